// round 3
// baseline (speedup 1.0000x reference)
#include <cuda_runtime.h>

// MaxPool2d k=2 s=2 valid, input (32,64,224,224) fp32 -> output (32,64,112,112).
// Pure HBM-streaming: 411 MB in + 103 MB out. Each thread computes 4 output
// pixels: 2x float4 loads from each of 2 input rows (all 16B-aligned), one
// float4 store. Windows are disjoint so no data is read twice.

#define NC_TOTAL   2048      // 32 * 64
#define IH         224
#define IW         224
#define OH         112
#define OW         112
#define IN_PLANE   (IH * IW)         // 50176
#define OUT_PLANE  (OH * OW)         // 12544
#define GROUPS_W   (OW / 4)          // 28 float4 groups per output row
#define TOTAL_THREADS (NC_TOTAL * OH * GROUPS_W)  // 6,422,528

__global__ __launch_bounds__(256)
void maxpool2d_k2s2_kernel(const float* __restrict__ in, float* __restrict__ out) {
    int idx = blockIdx.x * blockDim.x + threadIdx.x;
    // Grid sized exactly: 6,422,528 / 256 = 25088 blocks, no bounds check needed,
    // but keep it for safety against future blockDim changes.
    if (idx >= TOTAL_THREADS) return;

    int w8 = idx % GROUPS_W;               // which group of 4 output cols
    int t  = idx / GROUPS_W;
    int oh = t % OH;
    int nc = t / OH;

    // Input: rows oh*2 and oh*2+1, cols [w8*8, w8*8+7]
    const float4* r0 = reinterpret_cast<const float4*>(
        in + (size_t)nc * IN_PLANE + (size_t)(oh * 2) * IW) + w8 * 2;
    const float4* r1 = r0 + (IW / 4);      // next input row = 56 float4s

    // Front-batch all 4 independent 128-bit loads for MLP.
    float4 a0 = r0[0];
    float4 a1 = r0[1];
    float4 b0 = r1[0];
    float4 b1 = r1[1];

    float4 o;
    o.x = fmaxf(fmaxf(a0.x, a0.y), fmaxf(b0.x, b0.y));
    o.y = fmaxf(fmaxf(a0.z, a0.w), fmaxf(b0.z, b0.w));
    o.z = fmaxf(fmaxf(a1.x, a1.y), fmaxf(b1.x, b1.y));
    o.w = fmaxf(fmaxf(a1.z, a1.w), fmaxf(b1.z, b1.w));

    reinterpret_cast<float4*>(out + (size_t)nc * OUT_PLANE + (size_t)oh * OW)[w8] = o;
}

extern "C" void kernel_launch(void* const* d_in, const int* in_sizes, int n_in,
                              void* d_out, int out_size) {
    const float* in = (const float*)d_in[0];
    float* out = (float*)d_out;
    int blocks = (TOTAL_THREADS + 255) / 256;   // 25088
    maxpool2d_k2s2_kernel<<<blocks, 256>>>(in, out);
}